// round 9
// baseline (speedup 1.0000x reference)
#include <cuda_runtime.h>
#include <cuda_bf16.h>
#include <cstdint>
#include <cstddef>

#define B_   16
#define S_   2048
#define D_   256
#define GD_  1024
#define L_   4
#define NTOK (B_*S_)
#define CL   8

// ---- scratch (device globals: no allocations allowed) ----
__device__ float g_h [(size_t)NTOK*D_];     // residual stream [B,S,D]   (32 MB)
__device__ float g_gx[(size_t)NTOK*GD_];    // gate preacts    [B,S,4D]  (128 MB)
__device__ float g_mu[NTOK];
__device__ float g_rs[NTOK];

typedef unsigned long long ull;

__device__ __forceinline__ ull pack2(float x, float y){
    ull r; asm("mov.b64 %0,{%1,%2};" : "=l"(r) : "f"(x), "f"(y)); return r;
}
__device__ __forceinline__ float2 unpack2(ull v){
    float2 f; asm("mov.b64 {%0,%1},%2;" : "=f"(f.x), "=f"(f.y) : "l"(v)); return f;
}
__device__ __forceinline__ void fma2(ull& d, ull a, ull b){
    asm("fma.rn.f32x2 %0,%1,%2,%0;" : "+l"(d) : "l"(a), "l"(b));
}

// ============================================================
// 1) input projection: h = concat(x, time_feats) @ in_W + in_b
// ============================================================
__global__ void k_inproj(const float* __restrict__ x, const float* __restrict__ tf,
                         const float* __restrict__ W, const float* __restrict__ b)
{
    int t = blockIdx.x;          // token 0..32767
    int d = threadIdx.x;         // 0..255
    float acc = b[d] + x[t]*W[d];
    const float* tft = tf + (size_t)t*6;
    #pragma unroll
    for(int f=0; f<6; f++) acc = fmaf(tft[f], W[(f+1)*D_ + d], acc);
    g_h[(size_t)t*D_ + d] = acc;
}

// ============================================================
// 2) per-token layernorm stats (mean, rstd): 1 warp per token
// ============================================================
__global__ void k_lnstats()
{
    int warp = threadIdx.x >> 5, lane = threadIdx.x & 31;
    int t = blockIdx.x*8 + warp;
    const float4* p = (const float4*)(g_h + (size_t)t*D_) + lane*2;
    float4 v0 = p[0], v1 = p[1];
    float s = v0.x+v0.y+v0.z+v0.w + v1.x+v1.y+v1.z+v1.w;
    float q = v0.x*v0.x+v0.y*v0.y+v0.z*v0.z+v0.w*v0.w
            + v1.x*v1.x+v1.y*v1.y+v1.z*v1.z+v1.w*v1.w;
    #pragma unroll
    for(int o=16;o;o>>=1){ s += __shfl_xor_sync(~0u,s,o); q += __shfl_xor_sync(~0u,q,o); }
    if(lane==0){
        float mu  = s * (1.f/256.f);
        float var = q * (1.f/256.f) - mu*mu;
        g_mu[t] = mu;
        g_rs[t] = rsqrtf(var + 1e-5f);
    }
}

// ============================================================
// 3) gx = (LN(h)*g+b) @ Wx + bg   (128x128 tile, K-chunk 8, f32x2 accs)
// ============================================================
__global__ __launch_bounds__(256)
void k_gemm(const float* __restrict__ Wx, const float* __restrict__ bg,
            const float* __restrict__ lng, const float* __restrict__ lnb)
{
    __shared__ __align__(16) float As[8*128];
    __shared__ __align__(16) float Bs[8*128];

    int tid = threadIdx.x;
    int m0 = blockIdx.y*128, n0 = blockIdx.x*128;
    int tx = tid & 15, ty = tid >> 4;

    ull acc[8][4];
    #pragma unroll
    for(int i=0;i<8;i++)
        #pragma unroll
        for(int j=0;j<4;j++) acc[i][j]=0ULL;

    int arow = tid>>1, akp = (tid&1)*4;
    float amu = g_mu[m0+arow], ars = g_rs[m0+arow];
    int bkk = tid>>5, bn = (tid&31)*4;

    for(int kb=0; kb<D_; kb+=8){
        float4 av = *(const float4*)(g_h + (size_t)(m0+arow)*D_ + kb + akp);
        float4 lg = *(const float4*)(lng + kb + akp);
        float4 lb = *(const float4*)(lnb + kb + akp);
        As[(akp+0)*128+arow] = (av.x-amu)*ars*lg.x + lb.x;
        As[(akp+1)*128+arow] = (av.y-amu)*ars*lg.y + lb.y;
        As[(akp+2)*128+arow] = (av.z-amu)*ars*lg.z + lb.z;
        As[(akp+3)*128+arow] = (av.w-amu)*ars*lg.w + lb.w;
        *(float4*)(Bs + bkk*128 + bn) =
            *(const float4*)(Wx + (size_t)(kb+bkk)*GD_ + n0 + bn);
        __syncthreads();
        #pragma unroll
        for(int kk=0; kk<8; kk++){
            float4 a0 = *(const float4*)(As + kk*128 + ty*8);
            float4 a1 = *(const float4*)(As + kk*128 + ty*8 + 4);
            const ull* b2 = (const ull*)(Bs + kk*128 + tx*8);
            ull bb0=b2[0], bb1=b2[1], bb2=b2[2], bb3=b2[3];
            float a[8] = {a0.x,a0.y,a0.z,a0.w,a1.x,a1.y,a1.z,a1.w};
            #pragma unroll
            for(int i=0;i<8;i++){
                ull a2 = pack2(a[i], a[i]);
                fma2(acc[i][0], a2, bb0);
                fma2(acc[i][1], a2, bb1);
                fma2(acc[i][2], a2, bb2);
                fma2(acc[i][3], a2, bb3);
            }
        }
        __syncthreads();
    }
    float4 bg0 = *(const float4*)(bg + n0 + tx*8);
    float4 bg1 = *(const float4*)(bg + n0 + tx*8 + 4);
    #pragma unroll
    for(int i=0;i<8;i++){
        float* C = g_gx + (size_t)(m0+ty*8+i)*GD_ + n0 + tx*8;
        float2 c0=unpack2(acc[i][0]), c1=unpack2(acc[i][1]);
        float2 c2=unpack2(acc[i][2]), c3=unpack2(acc[i][3]);
        float4 o0 = make_float4(c0.x+bg0.x, c0.y+bg0.y, c1.x+bg0.z, c1.y+bg0.w);
        float4 o1 = make_float4(c2.x+bg1.x, c2.y+bg1.y, c3.x+bg1.z, c3.y+bg1.w);
        *(float4*)C       = o0;
        *(float4*)(C + 4) = o1;
    }
}

// ============================================================
// 4) sLSTM recurrence — barrier-free cluster pipeline.
//    1 batch per 8-CTA cluster; CTA rank owns dims [rank*32, +32).
//    Warp w owns dims {rank*32+2w, +1}; its 8 gate-columns are
//    reduced warp-locally (shfl butterfly); lanes 0/1 do gating and
//    push h to all 8 CTAs (st.shared::cluster + mbarrier arrive).
//    Per step sync = ONE mbarrier parity wait. No __syncthreads.
// ============================================================
__global__ void __launch_bounds__(512,1) __cluster_dims__(CL,1,1)
k_slstm(const float* __restrict__ Wh)
{
    __shared__ __align__(16) float h_buf[2][256];   // double-buffered hidden state
    __shared__ __align__(8)  ull   mbar[2];         // per-buffer arrival barriers

    int tid  = threadIdx.x;
    int lane = tid & 31, warp = tid >> 5;
    uint32_t rank;
    asm("mov.u32 %0, %%cluster_ctarank;" : "=r"(rank));
    int batch = blockIdx.x >> 3;

    // ---- register-resident Wh: warp w -> 8 cols (2 dims x 4 gates),
    //      lane l -> k-pairs {2l, 2l+64, 2l+128, 2l+192}
    int dim0 = (int)rank*32 + 2*warp;
    ull w2[8][4];
    #pragma unroll
    for(int c=0;c<8;c++){
        int gc = (c>>1)*256 + dim0 + (c&1);
        #pragma unroll
        for(int j=0;j<4;j++){
            int k = 2*lane + 64*j;
            w2[c][j] = pack2(Wh[(size_t)k*GD_ + gc], Wh[(size_t)(k+1)*GD_ + gc]);
        }
    }

    uint32_t mb0 = (uint32_t)__cvta_generic_to_shared(&mbar[0]);
    uint32_t mb1 = (uint32_t)__cvta_generic_to_shared(&mbar[1]);

    if(tid < 256) h_buf[0][tid] = 0.f;
    if(tid == 0){
        asm volatile("mbarrier.init.shared.b64 [%0], %1;" :: "r"(mb0), "r"(256) : "memory");
        asm volatile("mbarrier.init.shared.b64 [%0], %1;" :: "r"(mb1), "r"(256) : "memory");
    }
    __syncthreads();
    asm volatile("barrier.cluster.arrive.aligned;" ::: "memory");
    asm volatile("barrier.cluster.wait.aligned;"   ::: "memory");

    // ---- gating-lane setup (lanes 0,1 of every warp)
    bool gl = (lane < 2);
    int dimg = dim0 + lane;                          // my hidden dim (if gl)
    const float* gx_b = g_gx + (size_t)batch*S_*GD_;
    float*       h_bp = g_h  + (size_t)batch*S_*D_;

    float c_st=0.f, n_st=0.f, m_st=0.f;
    float gxi=0.f, gxf=0.f, gxz=0.f, gxo=0.f, hres=0.f;
    if(gl){
        gxi = gx_b[      dimg]; gxf = gx_b[256 + dimg];
        gxz = gx_b[512 + dimg]; gxo = gx_b[768 + dimg];
        hres = h_bp[dimg];
    }
    uint32_t hb_l[2];
    hb_l[0] = (uint32_t)__cvta_generic_to_shared(&h_buf[0][(int)rank*32 + 2*warp + lane]);
    hb_l[1] = (uint32_t)__cvta_generic_to_shared(&h_buf[1][(int)rank*32 + 2*warp + lane]);
    uint32_t mb_l[2] = {mb0, mb1};

    int ph0 = 0, ph1 = 0;   // consumed-phase counters per buffer

    for(int t=0; t<S_; t++){
        int cur = t & 1, nxt = cur ^ 1;

        // ---- wait for all 256 arrivals of this buffer's phase
        if(t > 0){
            uint32_t mb = mb_l[cur];
            uint32_t par = (uint32_t)((cur ? ph1 : ph0) & 1);
            asm volatile(
                "{\n\t.reg .pred P;\n\t"
                "WL_%=:\n\t"
                "mbarrier.try_wait.parity.acquire.cluster.shared::cta.b64 P, [%0], %1, 0x989680;\n\t"
                "@P bra.uni WD_%=;\n\t"
                "bra.uni WL_%=;\n\t"
                "WD_%=:\n\t}"
                :: "r"(mb), "r"(par) : "memory");
            if(cur) ph1++; else ph0++;
        }

        // ---- warp-local matvec partials: 8 cols over my 8 k's
        const ull* hb2 = (const ull*)h_buf[cur] + lane;   // k-pair {2l,2l+1}
        ull h0 = hb2[0], h1 = hb2[32], h2v = hb2[64], h3 = hb2[96];
        float v[8];
        #pragma unroll
        for(int c=0;c<8;c++){
            ull a = 0ULL;
            fma2(a, h0,  w2[c][0]);
            fma2(a, h1,  w2[c][1]);
            fma2(a, h2v, w2[c][2]);
            fma2(a, h3,  w2[c][3]);
            float2 p = unpack2(a);
            v[c] = p.x + p.y;
        }
        // ---- butterfly reduce over 32 lanes (also a warp sync point)
        #pragma unroll
        for(int m=16; m; m>>=1){
            #pragma unroll
            for(int c=0;c<8;c++)
                v[c] += __shfl_xor_sync(0xffffffffu, v[c], m);
        }

        // ---- gating + push (lanes 0,1)
        if(gl){
            float i_t = v[    lane] + gxi;
            float f_t = v[2 + lane] + gxf;
            float z_t = v[4 + lane] + gxz;
            float o_t = v[6 + lane] + gxo;

            float m_new = fmaxf(f_t + m_st, i_t);
            float ip = __expf(i_t - m_new);
            float fp = __expf(f_t + m_st - m_new);
            m_st = m_new;
            float tz;
            asm("tanh.approx.f32 %0, %1;" : "=f"(tz) : "f"(z_t));
            c_st = fp*c_st + ip*tz;
            n_st = fp*n_st + ip;
            float sig = __frcp_rn(1.f + __expf(-o_t));
            float hval = sig * c_st * __frcp_rn(fmaxf(fabsf(n_st), 1.f));

            // prefetch next step's gx + residual (latency hidden over the step)
            if(t+1 < S_){
                const float* g2 = gx_b + (size_t)(t+1)*GD_;
                gxi = g2[      dimg]; gxf = g2[256 + dimg];
                gxz = g2[512 + dimg]; gxo = g2[768 + dimg];
            }
            h_bp[(size_t)t*D_ + dimg] = hres + hval;     // residual out
            if(t+1 < S_) hres = h_bp[(size_t)(t+1)*D_ + dimg];

            // push h to all 8 CTAs' buffer[nxt] then release-arrive their mbar[nxt]
            uint32_t la_st = hb_l[nxt], la_mb = mb_l[nxt];
            #pragma unroll
            for(int r=0; r<CL; r++){
                uint32_t ra, rm;
                asm volatile("mapa.shared::cluster.u32 %0, %1, %2;" : "=r"(ra) : "r"(la_st), "r"(r));
                asm volatile("st.shared::cluster.f32 [%0], %1;" :: "r"(ra), "f"(hval) : "memory");
                asm volatile("mapa.shared::cluster.u32 %0, %1, %2;" : "=r"(rm) : "r"(la_mb), "r"(r));
                asm volatile("mbarrier.arrive.release.cluster.shared::cluster.b64 _, [%0];"
                             :: "r"(rm) : "memory");
            }
        }
    }

    // keep cluster SMEM alive until every CTA's last pushes have landed
    asm volatile("barrier.cluster.arrive.aligned;" ::: "memory");
    asm volatile("barrier.cluster.wait.aligned;"   ::: "memory");
}

// ============================================================
// 5) head: out[b] = h[b, S-1, :] @ fc_W + fc_b
// ============================================================
__global__ void k_head(const float* __restrict__ fcW, const float* __restrict__ fcb,
                       float* __restrict__ out)
{
    __shared__ float red[8];
    int b = blockIdx.x, tid = threadIdx.x;
    int lane = tid & 31, warp = tid >> 5;
    float v = g_h[((size_t)b*S_ + (S_-1))*D_ + tid] * fcW[tid];
    #pragma unroll
    for(int o=16;o;o>>=1) v += __shfl_xor_sync(~0u, v, o);
    if(lane==0) red[warp] = v;
    __syncthreads();
    if(tid==0){
        float s = 0.f;
        #pragma unroll
        for(int w=0;w<8;w++) s += red[w];
        out[b] = s + fcb[0];
    }
}

// ============================================================
extern "C" void kernel_launch(void* const* d_in, const int* in_sizes, int n_in,
                              void* d_out, int out_size)
{
    (void)in_sizes; (void)n_in; (void)out_size;
    const float* x    = (const float*)d_in[0];
    const float* tf   = (const float*)d_in[1];
    const float* in_W = (const float*)d_in[2];
    const float* in_b = (const float*)d_in[3];
    const float* ln_g = (const float*)d_in[4];
    const float* ln_b = (const float*)d_in[5];
    const float* Wx   = (const float*)d_in[6];
    const float* Wh   = (const float*)d_in[7];
    const float* bg   = (const float*)d_in[8];
    const float* fc_W = (const float*)d_in[9];
    const float* fc_b = (const float*)d_in[10];
    float* out = (float*)d_out;

    k_inproj<<<NTOK, 256>>>(x, tf, in_W, in_b);
    for(int l=0; l<L_; l++){
        k_lnstats<<<NTOK/8, 256>>>();
        k_gemm<<<dim3(8,256), 256>>>(Wx + (size_t)l*D_*GD_, bg + (size_t)l*GD_,
                                     ln_g + (size_t)l*D_, ln_b + (size_t)l*D_);
        k_slstm<<<B_*CL, 512>>>(Wh + (size_t)l*D_*GD_);
    }
    k_head<<<B_, 256>>>(fc_W, fc_b, out);
}

// round 10
// speedup vs baseline: 3.1510x; 3.1510x over previous
#include <cuda_runtime.h>
#include <cuda_bf16.h>
#include <cstdint>
#include <cstddef>

#define B_   16
#define S_   2048
#define D_   256
#define GD_  1024
#define L_   4
#define NTOK (B_*S_)
#define CL   8

// ---- scratch (device globals: no allocations allowed) ----
__device__ float g_h  [(size_t)NTOK*D_];      // residual stream [B,S,D]
__device__ float g_gx [(size_t)NTOK*GD_];     // gate preacts    [B,S,4D]
__device__ float g_mu [NTOK];
__device__ float g_rs [NTOK];
__device__ float g_whT[(size_t)L_*GD_*D_];    // Wh transposed: [l][col][k]

typedef unsigned long long ull;

__device__ __forceinline__ ull pack2(float x, float y){
    ull r; asm("mov.b64 %0,{%1,%2};" : "=l"(r) : "f"(x), "f"(y)); return r;
}
__device__ __forceinline__ float2 unpack2(ull v){
    float2 f; asm("mov.b64 {%0,%1},%2;" : "=f"(f.x), "=f"(f.y) : "l"(v)); return f;
}
__device__ __forceinline__ void fma2(ull& d, ull a, ull b){
    asm("fma.rn.f32x2 %0,%1,%2,%0;" : "+l"(d) : "l"(a), "l"(b));
}
__device__ __forceinline__ void add2(ull& d, ull a){
    asm("add.rn.f32x2 %0,%0,%1;" : "+l"(d) : "l"(a));
}
__device__ __forceinline__ float frcp(float x){
    float r; asm("rcp.approx.f32 %0,%1;" : "=f"(r) : "f"(x)); return r;
}
__device__ __forceinline__ float ftanh(float x){
    float r; asm("tanh.approx.f32 %0,%1;" : "=f"(r) : "f"(x)); return r;
}

// ============================================================
// 1) input projection
// ============================================================
__global__ void k_inproj(const float* __restrict__ x, const float* __restrict__ tf,
                         const float* __restrict__ W, const float* __restrict__ b)
{
    int t = blockIdx.x, d = threadIdx.x;
    float acc = b[d] + x[t]*W[d];
    const float* tft = tf + (size_t)t*6;
    #pragma unroll
    for(int f=0; f<6; f++) acc = fmaf(tft[f], W[(f+1)*D_ + d], acc);
    g_h[(size_t)t*D_ + d] = acc;
}

// ============================================================
// 2) per-token layernorm stats
// ============================================================
__global__ void k_lnstats()
{
    int warp = threadIdx.x >> 5, lane = threadIdx.x & 31;
    int t = blockIdx.x*8 + warp;
    const float4* p = (const float4*)(g_h + (size_t)t*D_) + lane*2;
    float4 v0 = p[0], v1 = p[1];
    float s = v0.x+v0.y+v0.z+v0.w + v1.x+v1.y+v1.z+v1.w;
    float q = v0.x*v0.x+v0.y*v0.y+v0.z*v0.z+v0.w*v0.w
            + v1.x*v1.x+v1.y*v1.y+v1.z*v1.z+v1.w*v1.w;
    #pragma unroll
    for(int o=16;o;o>>=1){ s += __shfl_xor_sync(~0u,s,o); q += __shfl_xor_sync(~0u,q,o); }
    if(lane==0){
        float mu  = s * (1.f/256.f);
        float var = q * (1.f/256.f) - mu*mu;
        g_mu[t] = mu;
        g_rs[t] = rsqrtf(var + 1e-5f);
    }
}

// ============================================================
// 2b) Wh transpose: g_whT[l][c][k] = Wh[l][k][c]
// ============================================================
__global__ void k_whT(const float* __restrict__ Wh)
{
    __shared__ float tile[32][33];
    int l = blockIdx.z;
    const float* src = Wh + (size_t)l*D_*GD_;
    float* dst = g_whT + (size_t)l*GD_*D_;
    int c0 = blockIdx.x*32, k0 = blockIdx.y*32;
    int tx = threadIdx.x, ty = threadIdx.y;
    #pragma unroll
    for(int r=0;r<32;r+=8) tile[ty+r][tx] = src[(size_t)(k0+ty+r)*GD_ + c0+tx];
    __syncthreads();
    #pragma unroll
    for(int r=0;r<32;r+=8) dst[(size_t)(c0+ty+r)*D_ + k0+tx] = tile[tx][ty+r];
}

// ============================================================
// 3) gx = (LN(h)*g+b) @ Wx + bg   (128x128 tile, f32x2 accs)
// ============================================================
__global__ __launch_bounds__(256)
void k_gemm(const float* __restrict__ Wx, const float* __restrict__ bg,
            const float* __restrict__ lng, const float* __restrict__ lnb)
{
    __shared__ __align__(16) float As[8*128];
    __shared__ __align__(16) float Bs[8*128];

    int tid = threadIdx.x;
    int m0 = blockIdx.y*128, n0 = blockIdx.x*128;
    int tx = tid & 15, ty = tid >> 4;

    ull acc[8][4];
    #pragma unroll
    for(int i=0;i<8;i++)
        #pragma unroll
        for(int j=0;j<4;j++) acc[i][j]=0ULL;

    int arow = tid>>1, akp = (tid&1)*4;
    float amu = g_mu[m0+arow], ars = g_rs[m0+arow];
    int bkk = tid>>5, bn = (tid&31)*4;

    for(int kb=0; kb<D_; kb+=8){
        float4 av = *(const float4*)(g_h + (size_t)(m0+arow)*D_ + kb + akp);
        float4 lg = *(const float4*)(lng + kb + akp);
        float4 lb = *(const float4*)(lnb + kb + akp);
        As[(akp+0)*128+arow] = (av.x-amu)*ars*lg.x + lb.x;
        As[(akp+1)*128+arow] = (av.y-amu)*ars*lg.y + lb.y;
        As[(akp+2)*128+arow] = (av.z-amu)*ars*lg.z + lb.z;
        As[(akp+3)*128+arow] = (av.w-amu)*ars*lg.w + lb.w;
        *(float4*)(Bs + bkk*128 + bn) =
            *(const float4*)(Wx + (size_t)(kb+bkk)*GD_ + n0 + bn);
        __syncthreads();
        #pragma unroll
        for(int kk=0; kk<8; kk++){
            float4 a0 = *(const float4*)(As + kk*128 + ty*8);
            float4 a1 = *(const float4*)(As + kk*128 + ty*8 + 4);
            const ull* b2 = (const ull*)(Bs + kk*128 + tx*8);
            ull bb0=b2[0], bb1=b2[1], bb2=b2[2], bb3=b2[3];
            float a[8] = {a0.x,a0.y,a0.z,a0.w,a1.x,a1.y,a1.z,a1.w};
            #pragma unroll
            for(int i=0;i<8;i++){
                ull a2 = pack2(a[i], a[i]);
                fma2(acc[i][0], a2, bb0);
                fma2(acc[i][1], a2, bb1);
                fma2(acc[i][2], a2, bb2);
                fma2(acc[i][3], a2, bb3);
            }
        }
        __syncthreads();
    }
    float4 bg0 = *(const float4*)(bg + n0 + tx*8);
    float4 bg1 = *(const float4*)(bg + n0 + tx*8 + 4);
    #pragma unroll
    for(int i=0;i<8;i++){
        float* C = g_gx + (size_t)(m0+ty*8+i)*GD_ + n0 + tx*8;
        float2 c0=unpack2(acc[i][0]), c1=unpack2(acc[i][1]);
        float2 c2=unpack2(acc[i][2]), c3=unpack2(acc[i][3]);
        *(float4*)C       = make_float4(c0.x+bg0.x, c0.y+bg0.y, c1.x+bg0.z, c1.y+bg0.w);
        *(float4*)(C + 4) = make_float4(c2.x+bg1.x, c2.y+bg1.y, c3.x+bg1.z, c3.y+bg1.w);
    }
}

// ============================================================
// 4) sLSTM recurrence — cluster 8, 256 threads/CTA.
//    CTA rank owns dims [rank*32,+32) -> 128 gate cols.
//    2 threads per col (k-halves, 16-float interleave), weights in regs.
//    Per step: 32 LDS.128 + 64 fma2 + 1 shfl + STS + __syncthreads
//              + 32-lane gating + 8 remote st + barrier.cluster.
//    gx/residual streamed through a depth-4 cp.async ring (warp 0).
// ============================================================

// one recurrence step; CUR/NXT are compile-time 0/1, RA = 8 hoisted remote addrs
#define SLSTM_STEP(T, CUR, NXT, RA)                                            \
{                                                                              \
    /* matvec: v = sum_k h[k] * WhT[c][k] over my k-half */                    \
    const ull* hu = (const ull*)h_buf[CUR];                                    \
    ull a0=0ULL, a1=0ULL, a2v=0ULL, a3=0ULL;                                   \
    _Pragma("unroll")                                                          \
    for(int q=0; q<16; q++){                                                   \
        ulonglong2 U = *(const ulonglong2*)(hu + 8*q + 4*s);                   \
        ulonglong2 V = *(const ulonglong2*)(hu + 8*q + 4*s + 2);               \
        fma2(a0,  U.x, w[4*q+0]);                                              \
        fma2(a1,  U.y, w[4*q+1]);                                              \
        fma2(a2v, V.x, w[4*q+2]);                                              \
        fma2(a3,  V.y, w[4*q+3]);                                              \
    }                                                                          \
    add2(a0, a1); add2(a2v, a3); add2(a0, a2v);                                \
    float2 pp = unpack2(a0);                                                   \
    float v = pp.x + pp.y;                                                     \
    v += __shfl_xor_sync(0xffffffffu, v, 16);                                  \
    if(lane < 16) g_arr[warp*16 + lane] = v;                                   \
    __syncthreads();                                                           \
    if(warp == 0){                                                             \
        int slot = (T) & 3;                                                    \
        asm volatile("cp.async.wait_group 3;" ::: "memory");                   \
        float gxi = gxbuf[slot][      lane];                                   \
        float gxf = gxbuf[slot][ 32 + lane];                                   \
        float gxz = gxbuf[slot][ 64 + lane];                                   \
        float gxo = gxbuf[slot][ 96 + lane];                                   \
        float hres = hrbuf[slot][lane];                                        \
        /* slot now reusable: prefetch T+4 */                                  \
        if((T)+4 < S_){                                                        \
            uint32_t dgx = (uint32_t)__cvta_generic_to_shared(&gxbuf[slot][lane*4]); \
            const float* sgx = gx_b + (size_t)((T)+4)*GD_ + gsrc;              \
            asm volatile("cp.async.cg.shared.global [%0], [%1], 16;"           \
                         :: "r"(dgx), "l"(sgx));                               \
            if(lane < 8){                                                      \
                uint32_t dhr = (uint32_t)__cvta_generic_to_shared(&hrbuf[slot][lane*4]); \
                const float* shr = h_bp + (size_t)((T)+4)*D_ + (int)rank*32 + lane*4; \
                asm volatile("cp.async.cg.shared.global [%0], [%1], 16;"       \
                             :: "r"(dhr), "l"(shr));                           \
            }                                                                  \
        }                                                                      \
        asm volatile("cp.async.commit_group;" ::: "memory");                   \
        /* gating */                                                           \
        float i_t = g_arr[      lane] + gxi;                                   \
        float f_t = g_arr[ 32 + lane] + gxf;                                   \
        float z_t = g_arr[ 64 + lane] + gxz;                                   \
        float o_t = g_arr[ 96 + lane] + gxo;                                   \
        float m_new = fmaxf(f_t + m_st, i_t);                                  \
        float ip = __expf(i_t - m_new);                                        \
        float fp = __expf(f_t + m_st - m_new);                                 \
        m_st = m_new;                                                          \
        c_st = fp*c_st + ip*ftanh(z_t);                                        \
        n_st = fp*n_st + ip;                                                   \
        float sig  = frcp(1.f + __expf(-o_t));                                 \
        float hval = sig * c_st * frcp(fmaxf(fabsf(n_st), 1.f));               \
        _Pragma("unroll")                                                      \
        for(int r=0; r<CL; r++)                                                \
            asm volatile("st.shared::cluster.f32 [%0], %1;"                    \
                         :: "r"(RA[r]), "f"(hval) : "memory");                 \
        h_bp[(size_t)(T)*D_ + (int)rank*32 + lane] = hres + hval;              \
    }                                                                          \
    asm volatile("barrier.cluster.arrive.aligned;" ::: "memory");              \
    asm volatile("barrier.cluster.wait.aligned;"   ::: "memory");              \
}

__global__ void __launch_bounds__(256,1) __cluster_dims__(CL,1,1)
k_slstm(int layer)
{
    __shared__ __align__(16) float h_buf[2][256];
    __shared__ __align__(16) float g_arr[128];
    __shared__ __align__(16) float gxbuf[4][128];
    __shared__ __align__(16) float hrbuf[4][32];

    int tid  = threadIdx.x;
    int lane = tid & 31, warp = tid >> 5;
    uint32_t rank;
    asm("mov.u32 %0, %%cluster_ctarank;" : "=r"(rank));
    int batch = blockIdx.x >> 3;

    // column / k-half assignment
    int cl_ = warp*16 + (lane & 15);     // local col 0..127
    int s   = lane >> 4;                 // k-half (16-float interleave)
    int gg  = cl_ >> 5, dl = cl_ & 31;
    int gcol = gg*256 + (int)rank*32 + dl;

    // register-resident Wh^T slice: 64 f32x2 (128 k-values of my column)
    const float* wr = g_whT + (size_t)layer*GD_*D_ + (size_t)gcol*D_;
    ull w[64];
    #pragma unroll
    for(int q=0; q<16; q++){
        float4 A  = *(const float4*)(wr + 16*q + 8*s);
        float4 Bv = *(const float4*)(wr + 16*q + 8*s + 4);
        w[4*q+0] = pack2(A.x,  A.y);
        w[4*q+1] = pack2(A.z,  A.w);
        w[4*q+2] = pack2(Bv.x, Bv.y);
        w[4*q+3] = pack2(Bv.z, Bv.w);
    }

    const float* gx_b = g_gx + (size_t)batch*S_*GD_;
    float*       h_bp = g_h  + (size_t)batch*S_*D_;
    int gsrc = ((lane>>3)<<8) + (int)rank*32 + ((4*lane)&31);  // gx src offset for my 16B

    // hoisted remote addresses (warp 0 only)
    uint32_t ra0[CL], ra1[CL];
    if(warp == 0){
        uint32_t la0 = (uint32_t)__cvta_generic_to_shared(&h_buf[0][(int)rank*32 + lane]);
        uint32_t la1 = (uint32_t)__cvta_generic_to_shared(&h_buf[1][(int)rank*32 + lane]);
        #pragma unroll
        for(int r=0; r<CL; r++){
            asm volatile("mapa.shared::cluster.u32 %0, %1, %2;" : "=r"(ra0[r]) : "r"(la0), "r"(r));
            asm volatile("mapa.shared::cluster.u32 %0, %1, %2;" : "=r"(ra1[r]) : "r"(la1), "r"(r));
        }
    }

    h_buf[0][tid] = 0.f;

    // prefill ring: steps 0..3 (4 groups)
    if(warp == 0){
        #pragma unroll
        for(int pt=0; pt<4; pt++){
            uint32_t dgx = (uint32_t)__cvta_generic_to_shared(&gxbuf[pt][lane*4]);
            const float* sgx = gx_b + (size_t)pt*GD_ + gsrc;
            asm volatile("cp.async.cg.shared.global [%0], [%1], 16;" :: "r"(dgx), "l"(sgx));
            if(lane < 8){
                uint32_t dhr = (uint32_t)__cvta_generic_to_shared(&hrbuf[pt][lane*4]);
                const float* shr = h_bp + (size_t)pt*D_ + (int)rank*32 + lane*4;
                asm volatile("cp.async.cg.shared.global [%0], [%1], 16;" :: "r"(dhr), "l"(shr));
            }
            asm volatile("cp.async.commit_group;" ::: "memory");
        }
    }
    __syncthreads();

    float c_st=0.f, n_st=0.f, m_st=0.f;

    for(int t=0; t<S_; t+=2){
        SLSTM_STEP(t,   0, 1, ra1)
        SLSTM_STEP(t+1, 1, 0, ra0)
    }
}

// ============================================================
// 5) head: out[b] = h[b, S-1, :] @ fc_W + fc_b
// ============================================================
__global__ void k_head(const float* __restrict__ fcW, const float* __restrict__ fcb,
                       float* __restrict__ out)
{
    __shared__ float red[8];
    int b = blockIdx.x, tid = threadIdx.x;
    int lane = tid & 31, warp = tid >> 5;
    float v = g_h[((size_t)b*S_ + (S_-1))*D_ + tid] * fcW[tid];
    #pragma unroll
    for(int o=16;o;o>>=1) v += __shfl_xor_sync(~0u, v, o);
    if(lane==0) red[warp] = v;
    __syncthreads();
    if(tid==0){
        float s = 0.f;
        #pragma unroll
        for(int w=0;w<8;w++) s += red[w];
        out[b] = s + fcb[0];
    }
}

// ============================================================
extern "C" void kernel_launch(void* const* d_in, const int* in_sizes, int n_in,
                              void* d_out, int out_size)
{
    (void)in_sizes; (void)n_in; (void)out_size;
    const float* x    = (const float*)d_in[0];
    const float* tf   = (const float*)d_in[1];
    const float* in_W = (const float*)d_in[2];
    const float* in_b = (const float*)d_in[3];
    const float* ln_g = (const float*)d_in[4];
    const float* ln_b = (const float*)d_in[5];
    const float* Wx   = (const float*)d_in[6];
    const float* Wh   = (const float*)d_in[7];
    const float* bg   = (const float*)d_in[8];
    const float* fc_W = (const float*)d_in[9];
    const float* fc_b = (const float*)d_in[10];
    float* out = (float*)d_out;

    k_inproj<<<NTOK, 256>>>(x, tf, in_W, in_b);
    k_whT<<<dim3(GD_/32, D_/32, L_), dim3(32,8)>>>(Wh);
    for(int l=0; l<L_; l++){
        k_lnstats<<<NTOK/8, 256>>>();
        k_gemm<<<dim3(8,256), 256>>>(Wx + (size_t)l*D_*GD_, bg + (size_t)l*GD_,
                                     ln_g + (size_t)l*D_, ln_b + (size_t)l*D_);
        k_slstm<<<B_*CL, 256>>>(l);
    }
    k_head<<<B_, 256>>>(fc_W, fc_b, out);
}